// round 3
// baseline (speedup 1.0000x reference)
#include <cuda_runtime.h>

// ---------------- problem constants ----------------
#define DF   16
#define BB   2
#define DIM  64
#define VOL  262144          // 64^3
#define OV   343000          // 70^3
#define ODIM 70

// output layout: (h, p, dpx, dpy, q, dqx, dqy) concatenated, fp32
#define OFF_H   0
#define OFF_P   (OFF_H   + (size_t)BB*OV)            // 686000
#define OFF_DPX (OFF_P   + (size_t)BB*DF*VOL)        // 9074608
#define OFF_DPY (OFF_DPX + (size_t)BB*DF*VOL)        // 17463216
#define OFF_Q   (OFF_DPY + (size_t)BB*DF*VOL)        // 25851824
#define OFF_DQX (OFF_Q   + (size_t)BB*DF*VOL)        // 34240432
#define OFF_DQY (OFF_DQX + (size_t)BB*DF*VOL)        // 42629040

// gradient scratch: [b, d, h, w] fields for p/q grads
__device__ float g_px[BB * VOL];
__device__ float g_py[BB * VOL];
__device__ float g_qx[BB * VOL];
__device__ float g_qy[BB * VOL];

// -------- sample with zero pad --------
__device__ __forceinline__ float Sv(const float* __restrict__ s, int d, int h, int w) {
    if ((unsigned)d < 64u && (unsigned)h < 64u && (unsigned)w < 64u)
        return __ldg(&s[(d << 12) + (h << 6) + w]);
    return 0.f;
}
// central difference along W at (d,h,w)
__device__ __forceinline__ float Gv(const float* __restrict__ s, int d, int h, int w) {
    return 0.5f * (Sv(s, d, h, w + 1) - Sv(s, d, h, w - 1));
}

// ===================== kernel 1: gradients + broadcast writes =====================
__global__ void grad_kernel(const float* __restrict__ p,
                            const float* __restrict__ q,
                            float* __restrict__ out) {
    int i = blockIdx.x * blockDim.x + threadIdx.x;
    if (i >= BB * VOL) return;
    int b = i >> 18;
    int r = i & (VOL - 1);
    int d = r >> 12;
    int h = (r >> 6) & 63;
    int w = r & 63;

    const float* sp = p + (((size_t)b * DF + 1) << 18);   // channel 1 of p
    const float* sq = q + (((size_t)b * DF + 1) << 18);   // channel 1 of q

    float gc  = Gv(sp, d, h, w);
    float g3x = Gv(sp, d - 1, h, w) + gc + Gv(sp, d + 1, h, w);
    float g3y = Gv(sp, d, h - 1, w) + gc + Gv(sp, d, h + 1, w);

    float hc  = Gv(sq, d, h, w);
    float h3x = Gv(sq, d - 1, h, w) + hc + Gv(sq, d + 1, h, w);
    float h3y = Gv(sq, d, h - 1, w) + hc + Gv(sq, d, h + 1, w);

    g_px[i] = g3x;  g_py[i] = g3y;
    g_qx[i] = h3x;  g_qy[i] = h3y;

    size_t ob = (size_t)b * DF * VOL + (size_t)r;
    float* dpx = out + OFF_DPX + ob;
    float* dpy = out + OFF_DPY + ob;
    float* dqx = out + OFF_DQX + ob;
    float* dqy = out + OFF_DQY + ob;
#pragma unroll
    for (int c = 0; c < DF; c++) {
        dpx[(size_t)c * VOL] = g3x;
        dpy[(size_t)c * VOL] = g3y;
        dqx[(size_t)c * VOL] = h3x;
        dqy[(size_t)c * VOL] = h3y;
    }
}

// ===================== kernel 2: boundary shell of the 70^3 output =====================
__global__ void shell_kernel(const float* __restrict__ W2, const float* __restrict__ b1,
                             const float* __restrict__ b2, const float* __restrict__ W3,
                             const float* __restrict__ b3, float* __restrict__ out) {
    __shared__ float sC[3];
    if (threadIdx.x == 0) {
        float a1[DF], a2[DF];
#pragma unroll
        for (int o = 0; o < DF; o++) a1[o] = fmaxf(b1[o], 0.f);
#pragma unroll
        for (int o = 0; o < DF; o++) {
            float s = b2[o];
#pragma unroll
            for (int c = 0; c < DF; c++) s += W2[o * DF + c] * a1[c];
            a2[o] = fmaxf(s, 0.f);
        }
        float c1 = b3[0], c2 = b3[0];
#pragma unroll
        for (int c = 0; c < DF; c++) c1 += W3[c] * a2[c];
#pragma unroll
        for (int c = 0; c < DF; c++) c2 += W3[c] * fmaxf(b2[c], 0.f);
        sC[0] = fmaxf(c1, 0.f);          // b1-zone constant
        sC[1] = fmaxf(c2, 0.f);          // b2-zone constant
        sC[2] = fmaxf(b3[0], 0.f);       // b3-zone constant
    }
    __syncthreads();

    int i = blockIdx.x * blockDim.x + threadIdx.x;
    if (i >= BB * OV) return;
    int r = i % OV;
    int d = r / 4900;
    int h = (r / ODIM) % ODIM;
    int w = r % ODIM;
    if (d >= 3 && d < 67 && h >= 3 && h < 67 && w >= 3 && w < 67) return; // interior kernel owns
    float v;
    if (d >= 2 && d < 68 && h >= 2 && h < 68 && w >= 2 && w < 68)      v = sC[0];
    else if (d >= 1 && d < 69 && h >= 1 && h < 69 && w >= 1 && w < 69) v = sC[1];
    else                                                               v = sC[2];
    out[OFF_H + i] = v;
}

// ===================== kernel 3: fused 3-layer pointwise MLP (interior) =====================
__global__ void __launch_bounds__(128) mlp_kernel(
    const float* __restrict__ p, const float* __restrict__ q,
    const float* __restrict__ W1, const float* __restrict__ b1,
    const float* __restrict__ W2, const float* __restrict__ b2,
    const float* __restrict__ W3, const float* __restrict__ b3v,
    float* __restrict__ out) {
    __shared__ float sWp[DF][DF];    // [c][o] p-block of W1
    __shared__ float sWq[DF][DF];    // [c][o] q-block of W1
    __shared__ float sW2t[DF][DF];   // [c][o]
    __shared__ float sw4[4][DF];     // folded grad weights: px, py, qx, qy
    __shared__ float sb1[DF], sb2[DF], sW3[DF];
    __shared__ float sb3;

    int t = threadIdx.x;
    if (t < DF) {
        int o = t;
        float px = 0.f, py = 0.f, qx = 0.f, qy = 0.f;
#pragma unroll
        for (int c = 0; c < DF; c++) {
            sWp[c][o] = W1[o * 96 + c];
            px += W1[o * 96 + 16 + c];
            py += W1[o * 96 + 32 + c];
            sWq[c][o] = W1[o * 96 + 48 + c];
            qx += W1[o * 96 + 64 + c];
            qy += W1[o * 96 + 80 + c];
            sW2t[c][o] = W2[o * DF + c];
        }
        sw4[0][o] = px; sw4[1][o] = py; sw4[2][o] = qx; sw4[3][o] = qy;
        sb1[o] = b1[o]; sb2[o] = b2[o]; sW3[o] = W3[o];
        if (o == 0) sb3 = b3v[0];
    }
    __syncthreads();

    // 2 * 64*64*16 thread-groups; each thread handles 4 consecutive w
    int i = blockIdx.x * blockDim.x + t;
    int b = i >> 16;
    int r = i & 65535;
    int x = r >> 10;            // d
    int y = (r >> 4) & 63;      // h
    int z = (r & 15) << 2;      // w base (float4-aligned)
    int sidx = (x << 12) + (y << 6) + z;
    int gidx = (b << 18) + sidx;

    float4 gpx = *(const float4*)&g_px[gidx];
    float4 gpy = *(const float4*)&g_py[gidx];
    float4 gqx = *(const float4*)&g_qx[gidx];
    float4 gqy = *(const float4*)&g_qy[gidx];

    float4 a1[DF];
#pragma unroll
    for (int o = 0; o < DF; o++) {
        float wx = sw4[0][o], wy = sw4[1][o], ux = sw4[2][o], uy = sw4[3][o], bb = sb1[o];
        a1[o].x = bb + wx * gpx.x + wy * gpy.x + ux * gqx.x + uy * gqy.x;
        a1[o].y = bb + wx * gpx.y + wy * gpy.y + ux * gqx.y + uy * gqy.y;
        a1[o].z = bb + wx * gpx.z + wy * gpy.z + ux * gqx.z + uy * gqy.z;
        a1[o].w = bb + wx * gpx.w + wy * gpy.w + ux * gqx.w + uy * gqy.w;
    }

    const float* pb = p + ((size_t)b * DF << 18) + sidx;
    const float* qb = q + ((size_t)b * DF << 18) + sidx;
#pragma unroll
    for (int c = 0; c < DF; c++) {
        float4 pv = *(const float4*)(pb + (size_t)c * VOL);
        float4 qv = *(const float4*)(qb + (size_t)c * VOL);
#pragma unroll
        for (int o = 0; o < DF; o++) {
            float wp = sWp[c][o], wq = sWq[c][o];
            a1[o].x += wp * pv.x + wq * qv.x;
            a1[o].y += wp * pv.y + wq * qv.y;
            a1[o].z += wp * pv.z + wq * qv.z;
            a1[o].w += wp * pv.w + wq * qv.w;
        }
    }
#pragma unroll
    for (int o = 0; o < DF; o++) {
        a1[o].x = fmaxf(a1[o].x, 0.f);
        a1[o].y = fmaxf(a1[o].y, 0.f);
        a1[o].z = fmaxf(a1[o].z, 0.f);
        a1[o].w = fmaxf(a1[o].w, 0.f);
    }

    float4 a2[DF];
#pragma unroll
    for (int o = 0; o < DF; o++) { float bb = sb2[o]; a2[o] = make_float4(bb, bb, bb, bb); }
#pragma unroll
    for (int c = 0; c < DF; c++) {
        float4 v = a1[c];
#pragma unroll
        for (int o = 0; o < DF; o++) {
            float w2 = sW2t[c][o];
            a2[o].x += w2 * v.x;
            a2[o].y += w2 * v.y;
            a2[o].z += w2 * v.z;
            a2[o].w += w2 * v.w;
        }
    }

    float4 yv = make_float4(sb3, sb3, sb3, sb3);
#pragma unroll
    for (int c = 0; c < DF; c++) {
        float w3 = sW3[c];
        yv.x += w3 * fmaxf(a2[c].x, 0.f);
        yv.y += w3 * fmaxf(a2[c].y, 0.f);
        yv.z += w3 * fmaxf(a2[c].z, 0.f);
        yv.w += w3 * fmaxf(a2[c].w, 0.f);
    }
    yv.x = fmaxf(yv.x, 0.f);
    yv.y = fmaxf(yv.y, 0.f);
    yv.z = fmaxf(yv.z, 0.f);
    yv.w = fmaxf(yv.w, 0.f);

    // write to out-h at (x+3, y+3, z+3..z+6)
    size_t ob = OFF_H + (size_t)b * OV + (size_t)(x + 3) * 4900 + (size_t)(y + 3) * ODIM + (z + 3);
    out[ob + 0] = yv.x;
    out[ob + 1] = yv.y;
    out[ob + 2] = yv.z;
    out[ob + 3] = yv.w;
}

// ===================== launch =====================
extern "C" void kernel_launch(void* const* d_in, const int* in_sizes, int n_in,
                              void* d_out, int out_size) {
    const float* p  = (const float*)d_in[0];
    const float* q  = (const float*)d_in[1];
    const float* W1 = (const float*)d_in[2];
    const float* b1 = (const float*)d_in[3];
    const float* W2 = (const float*)d_in[4];
    const float* b2 = (const float*)d_in[5];
    const float* W3 = (const float*)d_in[6];
    const float* b3 = (const float*)d_in[7];
    float* out = (float*)d_out;

    // echo p and q into the output tuple slots
    cudaMemcpyAsync(out + OFF_P, p, (size_t)BB * DF * VOL * sizeof(float),
                    cudaMemcpyDeviceToDevice, 0);
    cudaMemcpyAsync(out + OFF_Q, q, (size_t)BB * DF * VOL * sizeof(float),
                    cudaMemcpyDeviceToDevice, 0);

    // gradients (+ broadcast dpx/dpy/dqx/dqy outputs)
    grad_kernel<<<(BB * VOL + 255) / 256, 256>>>(p, q, out);

    // boundary shell of h
    shell_kernel<<<(BB * OV + 255) / 256, 256>>>(W2, b1, b2, W3, b3, out);

    // fused interior MLP (depends on grad scratch; same stream ordering)
    mlp_kernel<<<(BB * 64 * 64 * 16) / 128, 128>>>(p, q, W1, b1, W2, b2, W3, b3, out);
}

// round 4
// speedup vs baseline: 1.1334x; 1.1334x over previous
#include <cuda_runtime.h>

// ---------------- problem constants ----------------
#define DF   16
#define BB   2
#define DIM  64
#define VOL  262144          // 64^3
#define OV   343000          // 70^3
#define ODIM 70

// output layout: (h, p, dpx, dpy, q, dqx, dqy) concatenated, fp32
#define OFF_H   0
#define OFF_P   (OFF_H   + (size_t)BB*OV)
#define OFF_DPX (OFF_P   + (size_t)BB*DF*VOL)
#define OFF_DPY (OFF_DPX + (size_t)BB*DF*VOL)
#define OFF_Q   (OFF_DPY + (size_t)BB*DF*VOL)
#define OFF_DQX (OFF_Q   + (size_t)BB*DF*VOL)
#define OFF_DQY (OFF_DQX + (size_t)BB*DF*VOL)

// gradient scratch: [b, d, h, w] fields for p/q grads
__device__ float g_px[BB * VOL];
__device__ float g_py[BB * VOL];
__device__ float g_qx[BB * VOL];
__device__ float g_qy[BB * VOL];

// -------- sample with zero pad --------
__device__ __forceinline__ float Sv(const float* __restrict__ s, int d, int h, int w) {
    if ((unsigned)d < 64u && (unsigned)h < 64u && (unsigned)w < 64u)
        return __ldg(&s[(d << 12) + (h << 6) + w]);
    return 0.f;
}
__device__ __forceinline__ float Gv(const float* __restrict__ s, int d, int h, int w) {
    return 0.5f * (Sv(s, d, h, w + 1) - Sv(s, d, h, w - 1));
}

// ===================== kernel 1: gradient stencil -> scratch only =====================
__global__ void grad_kernel(const float* __restrict__ p,
                            const float* __restrict__ q) {
    int i = blockIdx.x * blockDim.x + threadIdx.x;
    if (i >= BB * VOL) return;
    int b = i >> 18;
    int r = i & (VOL - 1);
    int d = r >> 12;
    int h = (r >> 6) & 63;
    int w = r & 63;

    const float* sp = p + (((size_t)b * DF + 1) << 18);   // channel 1 of p
    const float* sq = q + (((size_t)b * DF + 1) << 18);   // channel 1 of q

    float gc  = Gv(sp, d, h, w);
    float g3x = Gv(sp, d - 1, h, w) + gc + Gv(sp, d + 1, h, w);
    float g3y = Gv(sp, d, h - 1, w) + gc + Gv(sp, d, h + 1, w);

    float hc  = Gv(sq, d, h, w);
    float h3x = Gv(sq, d - 1, h, w) + hc + Gv(sq, d + 1, h, w);
    float h3y = Gv(sq, d, h - 1, w) + hc + Gv(sq, d, h + 1, w);

    g_px[i] = g3x;  g_py[i] = g3y;
    g_qx[i] = h3x;  g_qy[i] = h3y;
}

// ===================== kernel 2: boundary shell of the 70^3 output =====================
__global__ void shell_kernel(const float* __restrict__ W2, const float* __restrict__ b1,
                             const float* __restrict__ b2, const float* __restrict__ W3,
                             const float* __restrict__ b3, float* __restrict__ out) {
    __shared__ float sC[3];
    if (threadIdx.x == 0) {
        float a1[DF], a2[DF];
#pragma unroll
        for (int o = 0; o < DF; o++) a1[o] = fmaxf(b1[o], 0.f);
#pragma unroll
        for (int o = 0; o < DF; o++) {
            float s = b2[o];
#pragma unroll
            for (int c = 0; c < DF; c++) s += W2[o * DF + c] * a1[c];
            a2[o] = fmaxf(s, 0.f);
        }
        float c1 = b3[0], c2 = b3[0];
#pragma unroll
        for (int c = 0; c < DF; c++) c1 += W3[c] * a2[c];
#pragma unroll
        for (int c = 0; c < DF; c++) c2 += W3[c] * fmaxf(b2[c], 0.f);
        sC[0] = fmaxf(c1, 0.f);
        sC[1] = fmaxf(c2, 0.f);
        sC[2] = fmaxf(b3[0], 0.f);
    }
    __syncthreads();

    int i = blockIdx.x * blockDim.x + threadIdx.x;
    if (i >= BB * OV) return;
    int r = i % OV;
    int d = r / 4900;
    int h = (r / ODIM) % ODIM;
    int w = r % ODIM;
    if (d >= 3 && d < 67 && h >= 3 && h < 67 && w >= 3 && w < 67) return;
    float v;
    if (d >= 2 && d < 68 && h >= 2 && h < 68 && w >= 2 && w < 68)      v = sC[0];
    else if (d >= 1 && d < 69 && h >= 1 && h < 69 && w >= 1 && w < 69) v = sC[1];
    else                                                               v = sC[2];
    out[OFF_H + i] = v;
}

// ===================== kernel 3: mega kernel =====================
// Per thread: one float4 of voxels. Streams p/q once (copy to output + accumulate
// layer-1), broadcasts the 4 grad fields to 16 channels each with STG.128, runs
// the fused 3-layer MLP, writes the interior of h.
__global__ void __launch_bounds__(256) mega_kernel(
    const float* __restrict__ p, const float* __restrict__ q,
    const float* __restrict__ W1, const float* __restrict__ b1,
    const float* __restrict__ W2, const float* __restrict__ b2,
    const float* __restrict__ W3, const float* __restrict__ b3v,
    float* __restrict__ out) {
    __shared__ float sWp[DF][DF];    // [c][o] p-block of W1
    __shared__ float sWq[DF][DF];    // [c][o] q-block of W1
    __shared__ float sW2t[DF][DF];   // [c][o]
    __shared__ float sw4[4][DF];     // folded grad weights: px, py, qx, qy
    __shared__ float sb1[DF], sb2[DF], sW3[DF];
    __shared__ float sb3;

    int t = threadIdx.x;
    if (t < DF) {
        int o = t;
        float px = 0.f, py = 0.f, qx = 0.f, qy = 0.f;
#pragma unroll
        for (int c = 0; c < DF; c++) {
            sWp[c][o] = W1[o * 96 + c];
            px += W1[o * 96 + 16 + c];
            py += W1[o * 96 + 32 + c];
            sWq[c][o] = W1[o * 96 + 48 + c];
            qx += W1[o * 96 + 64 + c];
            qy += W1[o * 96 + 80 + c];
            sW2t[c][o] = W2[o * DF + c];
        }
        sw4[0][o] = px; sw4[1][o] = py; sw4[2][o] = qx; sw4[3][o] = qy;
        sb1[o] = b1[o]; sb2[o] = b2[o]; sW3[o] = W3[o];
        if (o == 0) sb3 = b3v[0];
    }
    __syncthreads();

    int i = blockIdx.x * blockDim.x + t;      // 131072 threads total
    int b = i >> 16;
    int r = i & 65535;
    int x = r >> 10;            // d
    int y = (r >> 4) & 63;      // h
    int z = (r & 15) << 2;      // w base (float4-aligned)
    int sidx = (x << 12) + (y << 6) + z;
    int gidx = (b << 18) + sidx;

    // ---- grads: load once, broadcast to 16 channels x 4 fields ----
    float4 gpx = *(const float4*)&g_px[gidx];
    float4 gpy = *(const float4*)&g_py[gidx];
    float4 gqx = *(const float4*)&g_qx[gidx];
    float4 gqy = *(const float4*)&g_qy[gidx];

    size_t ob = (size_t)b * DF * VOL + (size_t)sidx;
    float* dpx = out + OFF_DPX + ob;
    float* dpy = out + OFF_DPY + ob;
    float* dqx = out + OFF_DQX + ob;
    float* dqy = out + OFF_DQY + ob;
#pragma unroll
    for (int c = 0; c < DF; c++) {
        *(float4*)(dpx + (size_t)c * VOL) = gpx;
        *(float4*)(dpy + (size_t)c * VOL) = gpy;
        *(float4*)(dqx + (size_t)c * VOL) = gqx;
        *(float4*)(dqy + (size_t)c * VOL) = gqy;
    }

    // ---- layer 1: grad contribution (folded weights) ----
    float4 a1[DF];
#pragma unroll
    for (int o = 0; o < DF; o++) {
        float wx = sw4[0][o], wy = sw4[1][o], ux = sw4[2][o], uy = sw4[3][o], bb = sb1[o];
        a1[o].x = bb + wx * gpx.x + wy * gpy.x + ux * gqx.x + uy * gqy.x;
        a1[o].y = bb + wx * gpx.y + wy * gpy.y + ux * gqx.y + uy * gqy.y;
        a1[o].z = bb + wx * gpx.z + wy * gpy.z + ux * gqx.z + uy * gqy.z;
        a1[o].w = bb + wx * gpx.w + wy * gpy.w + ux * gqx.w + uy * gqy.w;
    }

    // ---- stream p/q once: copy to output + accumulate layer 1 ----
    const float* pb = p + ((size_t)b * DF << 18) + sidx;
    const float* qb = q + ((size_t)b * DF << 18) + sidx;
    float* po = out + OFF_P + ob;
    float* qo = out + OFF_Q + ob;
#pragma unroll
    for (int c = 0; c < DF; c++) {
        float4 pv = *(const float4*)(pb + (size_t)c * VOL);
        float4 qv = *(const float4*)(qb + (size_t)c * VOL);
        *(float4*)(po + (size_t)c * VOL) = pv;
        *(float4*)(qo + (size_t)c * VOL) = qv;
#pragma unroll
        for (int o = 0; o < DF; o++) {
            float wp = sWp[c][o], wq = sWq[c][o];
            a1[o].x += wp * pv.x + wq * qv.x;
            a1[o].y += wp * pv.y + wq * qv.y;
            a1[o].z += wp * pv.z + wq * qv.z;
            a1[o].w += wp * pv.w + wq * qv.w;
        }
    }
#pragma unroll
    for (int o = 0; o < DF; o++) {
        a1[o].x = fmaxf(a1[o].x, 0.f);
        a1[o].y = fmaxf(a1[o].y, 0.f);
        a1[o].z = fmaxf(a1[o].z, 0.f);
        a1[o].w = fmaxf(a1[o].w, 0.f);
    }

    // ---- layers 2+3, lane at a time (caps register pressure) ----
    float4 yv;
    float* ylane = &yv.x;
#pragma unroll
    for (int l = 0; l < 4; l++) {
        float a2[DF];
#pragma unroll
        for (int o = 0; o < DF; o++) a2[o] = sb2[o];
#pragma unroll
        for (int c = 0; c < DF; c++) {
            float v = (&a1[c].x)[l];
#pragma unroll
            for (int o = 0; o < DF; o++) a2[o] += sW2t[c][o] * v;
        }
        float yy = sb3;
#pragma unroll
        for (int c = 0; c < DF; c++) yy += sW3[c] * fmaxf(a2[c], 0.f);
        ylane[l] = fmaxf(yy, 0.f);
    }

    // write to out-h at (x+3, y+3, z+3..z+6)
    size_t oh = OFF_H + (size_t)b * OV + (size_t)(x + 3) * 4900 + (size_t)(y + 3) * ODIM + (z + 3);
    out[oh + 0] = yv.x;
    out[oh + 1] = yv.y;
    out[oh + 2] = yv.z;
    out[oh + 3] = yv.w;
}

// ===================== launch =====================
extern "C" void kernel_launch(void* const* d_in, const int* in_sizes, int n_in,
                              void* d_out, int out_size) {
    const float* p  = (const float*)d_in[0];
    const float* q  = (const float*)d_in[1];
    const float* W1 = (const float*)d_in[2];
    const float* b1 = (const float*)d_in[3];
    const float* W2 = (const float*)d_in[4];
    const float* b2 = (const float*)d_in[5];
    const float* W3 = (const float*)d_in[6];
    const float* b3 = (const float*)d_in[7];
    float* out = (float*)d_out;

    grad_kernel<<<(BB * VOL + 255) / 256, 256>>>(p, q);
    shell_kernel<<<(BB * OV + 255) / 256, 256>>>(W2, b1, b2, W3, b3, out);
    mega_kernel<<<(BB * 64 * 64 * 16) / 256, 256>>>(p, q, W1, b1, W2, b2, W3, b3, out);
}